// round 1
// baseline (speedup 1.0000x reference)
#include <cuda_runtime.h>
#include <math.h>

#define B_  32
#define H_  56
#define W_  56
#define C_  256
#define NPIX (B_ * H_ * W_)   // 100352

// Scratch for pooled (avg, max) per pixel. Allocation-free per harness rules.
__device__ float2 g_pooled[NPIX];

// ---------------------------------------------------------------------------
// Kernel A: channel-wise avg + max pool. One warp per pixel.
// Each lane loads 8 floats via two float4 loads (warp-contiguous 512B each).
// ---------------------------------------------------------------------------
__global__ void pool_kernel(const float* __restrict__ x) {
    const int warp_in_block = threadIdx.x >> 5;
    const int lane = threadIdx.x & 31;
    const int pix = blockIdx.x * 8 + warp_in_block;   // 8 warps/block
    if (pix >= NPIX) return;

    const float4* __restrict__ x4 = reinterpret_cast<const float4*>(x) + (size_t)pix * (C_ / 4);

    float4 v0 = x4[lane];        // channels [lane*4 .. lane*4+3]
    float4 v1 = x4[32 + lane];   // channels [128 + lane*4 ..]

    float s = v0.x + v0.y + v0.z + v0.w + v1.x + v1.y + v1.z + v1.w;
    float m = fmaxf(fmaxf(fmaxf(v0.x, v0.y), fmaxf(v0.z, v0.w)),
                    fmaxf(fmaxf(v1.x, v1.y), fmaxf(v1.z, v1.w)));

    #pragma unroll
    for (int off = 16; off > 0; off >>= 1) {
        s += __shfl_xor_sync(0xffffffffu, s, off);
        m  = fmaxf(m, __shfl_xor_sync(0xffffffffu, m, off));
    }

    if (lane == 0) {
        g_pooled[pix] = make_float2(s * (1.0f / C_), m);
    }
}

// ---------------------------------------------------------------------------
// Kernel B: 7x7 conv over pooled (2->1 ch, SAME, zero pad) + sigmoid + scale.
// One block per (b, h) row of 56 pixels x 256 channels.
// ---------------------------------------------------------------------------
__global__ __launch_bounds__(256) void attn_scale_kernel(
    const float* __restrict__ x,
    const float* __restrict__ conv_w,   // [7][7][2] HWIO (O=1)
    const float* __restrict__ conv_b,   // [1]
    float* __restrict__ out)
{
    __shared__ float2 s_pool[7][W_];   // rows h-3..h+3
    __shared__ float  s_w[98];
    __shared__ float  s_attn[W_];

    const int tid = threadIdx.x;
    const int bh  = blockIdx.x;        // b*H_ + h
    const int b   = bh / H_;
    const int h   = bh % H_;

    // Load conv weights + pooled halo rows.
    if (tid < 98) s_w[tid] = conv_w[tid];

    // 7 rows * 56 cols = 392 entries; 256 threads -> 2 passes.
    for (int i = tid; i < 7 * W_; i += 256) {
        const int kr  = i / W_;          // 0..6
        const int col = i - kr * W_;
        const int row = h + kr - 3;
        float2 pv = make_float2(0.0f, 0.0f);
        if (row >= 0 && row < H_) {
            pv = g_pooled[(b * H_ + row) * W_ + col];
        }
        s_pool[kr][col] = pv;
    }
    __syncthreads();

    // Compute attention for this row's 56 pixels (threads 0..55).
    if (tid < W_) {
        float acc = conv_b[0];
        #pragma unroll
        for (int kh = 0; kh < 7; kh++) {
            const int row = h + kh - 3;
            if (row < 0 || row >= H_) continue;
            #pragma unroll
            for (int kw = 0; kw < 7; kw++) {
                const int col = tid + kw - 3;
                if (col < 0 || col >= W_) continue;
                const float2 pv = s_pool[kh][col];
                const float* wk = &s_w[(kh * 7 + kw) * 2];
                acc = fmaf(pv.x, wk[0], acc);
                acc = fmaf(pv.y, wk[1], acc);
            }
        }
        s_attn[tid] = 1.0f / (1.0f + expf(-acc));
    }
    __syncthreads();

    // Scale: 56 pixels * 64 float4 each = 3584 float4 for this row.
    const size_t row_base4 = (size_t)bh * W_ * (C_ / 4);
    const float4* __restrict__ x4 = reinterpret_cast<const float4*>(x) + row_base4;
    float4* __restrict__ o4 = reinterpret_cast<float4*>(out) + row_base4;

    #pragma unroll
    for (int it = 0; it < 14; it++) {
        const int idx = it * 256 + tid;        // 0..3583
        const int pix = idx >> 6;              // /64
        const float a = s_attn[pix];
        float4 v = x4[idx];
        v.x *= a; v.y *= a; v.z *= a; v.w *= a;
        o4[idx] = v;
    }
}

extern "C" void kernel_launch(void* const* d_in, const int* in_sizes, int n_in,
                              void* d_out, int out_size) {
    const float* x      = (const float*)d_in[0];
    const float* conv_w = (const float*)d_in[1];
    const float* conv_b = (const float*)d_in[2];
    float* out          = (float*)d_out;

    // Kernel A: 8 pixels per 256-thread block.
    pool_kernel<<<(NPIX + 7) / 8, 256>>>(x);

    // Kernel B: one block per (b, h) row.
    attn_scale_kernel<<<B_ * H_, 256>>>(x, conv_w, conv_b, out);
}

// round 2
// speedup vs baseline: 1.0465x; 1.0465x over previous
#include <cuda_runtime.h>
#include <math.h>

#define B_  32
#define H_  56
#define W_  56
#define C_  256
#define NPIX (B_ * H_ * W_)   // 100352

// Scratch for pooled (avg, max) per pixel.
__device__ float2 g_pooled[NPIX];

// ---------------------------------------------------------------------------
// Kernel A: channel-wise avg + max pool. 4 pixels per warp, all 8 LDG.128
// front-batched per thread for high MLP. Default cache policy: we WANT x to
// land in L2 so the attn kernel's re-read hits.
// ---------------------------------------------------------------------------
__global__ __launch_bounds__(256) void pool_kernel(const float* __restrict__ x) {
    const int warp_in_block = threadIdx.x >> 5;
    const int lane = threadIdx.x & 31;
    const int pix0 = (blockIdx.x * 8 + warp_in_block) * 4;   // 4 pixels/warp
    if (pix0 >= NPIX) return;

    const float4* __restrict__ x4 =
        reinterpret_cast<const float4*>(x) + (size_t)pix0 * (C_ / 4);

    // Front-batch all 8 independent 16B loads (MLP=8).
    float4 v[8];
    #pragma unroll
    for (int p = 0; p < 4; p++) {
        v[2 * p]     = x4[p * 64 + lane];
        v[2 * p + 1] = x4[p * 64 + 32 + lane];
    }

    float s[4], m[4];
    #pragma unroll
    for (int p = 0; p < 4; p++) {
        const float4 a = v[2 * p], b = v[2 * p + 1];
        s[p] = a.x + a.y + a.z + a.w + b.x + b.y + b.z + b.w;
        m[p] = fmaxf(fmaxf(fmaxf(a.x, a.y), fmaxf(a.z, a.w)),
                     fmaxf(fmaxf(b.x, b.y), fmaxf(b.z, b.w)));
    }

    // 4 independent butterfly reductions (latency overlapped).
    #pragma unroll
    for (int off = 16; off > 0; off >>= 1) {
        #pragma unroll
        for (int p = 0; p < 4; p++) {
            s[p] += __shfl_xor_sync(0xffffffffu, s[p], off);
            m[p]  = fmaxf(m[p], __shfl_xor_sync(0xffffffffu, m[p], off));
        }
    }

    if (lane < 4) {
        // lane p writes pixel pix0+p (lanes all hold the full reduction)
        g_pooled[pix0 + lane] = make_float2(s[lane] * (1.0f / C_), m[lane]);
    }
}

// ---------------------------------------------------------------------------
// Kernel B: 7x7 conv over pooled (2->1 ch, SAME, zero pad) + sigmoid + scale.
// One block per (b, h) row. x re-read with __ldcs (evict-first: line is dead
// after), out written with __stcs (streaming: don't evict x from L2).
// ---------------------------------------------------------------------------
__global__ __launch_bounds__(256) void attn_scale_kernel(
    const float* __restrict__ x,
    const float* __restrict__ conv_w,   // [7][7][2] HWIO (O=1)
    const float* __restrict__ conv_b,   // [1]
    float* __restrict__ out)
{
    __shared__ float2 s_pool[7][W_];   // rows h-3..h+3
    __shared__ float  s_w[98];
    __shared__ float  s_attn[W_];

    const int tid = threadIdx.x;
    const int bh  = blockIdx.x;        // b*H_ + h
    const int b   = bh / H_;
    const int h   = bh % H_;

    if (tid < 98) s_w[tid] = conv_w[tid];

    // 7 rows * 56 cols = 392 entries; 256 threads -> 2 passes.
    for (int i = tid; i < 7 * W_; i += 256) {
        const int kr  = i / W_;          // 0..6
        const int col = i - kr * W_;
        const int row = h + kr - 3;
        float2 pv = make_float2(0.0f, 0.0f);
        if (row >= 0 && row < H_) {
            pv = g_pooled[(b * H_ + row) * W_ + col];
        }
        s_pool[kr][col] = pv;
    }
    __syncthreads();

    // Attention for this row's 56 pixels (threads 0..55).
    if (tid < W_) {
        float acc = conv_b[0];
        #pragma unroll
        for (int kh = 0; kh < 7; kh++) {
            const int row = h + kh - 3;
            if (row < 0 || row >= H_) continue;
            #pragma unroll
            for (int kw = 0; kw < 7; kw++) {
                const int col = tid + kw - 3;
                if (col < 0 || col >= W_) continue;
                const float2 pv = s_pool[kh][col];
                const float* wk = &s_w[(kh * 7 + kw) * 2];
                acc = fmaf(pv.x, wk[0], acc);
                acc = fmaf(pv.y, wk[1], acc);
            }
        }
        s_attn[tid] = 1.0f / (1.0f + expf(-acc));
    }
    __syncthreads();

    // Scale: 56 pixels * 64 float4 = 3584 float4 for this row.
    const size_t row_base4 = (size_t)bh * W_ * (C_ / 4);
    const float4* __restrict__ x4 = reinterpret_cast<const float4*>(x) + row_base4;
    float4* __restrict__ o4 = reinterpret_cast<float4*>(out) + row_base4;

    #pragma unroll
    for (int it = 0; it < 14; it++) {
        const int idx = it * 256 + tid;        // 0..3583
        const int pix = idx >> 6;              // /64
        const float a = s_attn[pix];
        float4 v = __ldcs(&x4[idx]);           // evict-first read (dead after)
        v.x *= a; v.y *= a; v.z *= a; v.w *= a;
        __stcs(&o4[idx], v);                   // streaming store (don't pollute L2)
    }
}

extern "C" void kernel_launch(void* const* d_in, const int* in_sizes, int n_in,
                              void* d_out, int out_size) {
    const float* x      = (const float*)d_in[0];
    const float* conv_w = (const float*)d_in[1];
    const float* conv_b = (const float*)d_in[2];
    float* out          = (float*)d_out;

    // Kernel A: 32 pixels per 256-thread block (4 per warp).
    pool_kernel<<<(NPIX + 31) / 32, 256>>>(x);

    // Kernel B: one block per (b, h) row.
    attn_scale_kernel<<<B_ * H_, 256>>>(x, conv_w, conv_b, out);
}